// round 2
// baseline (speedup 1.0000x reference)
#include <cuda_runtime.h>
#include <math.h>

#define NMAX 50000
#define EMAX 600000
#define F    128
#define NCLSK 40
#define BN_EPS 1e-5f

// ---------------- scratch (device globals; no allocation allowed) ----------------
__device__ float  g_agg [NMAX * F];
__device__ float  g_hlin[NMAX * F];
__device__ float  g_h   [NMAX * F];
__device__ int    g_deg [NMAX];
__device__ int    g_off [NMAX + 1];
__device__ int    g_cur [NMAX];
__device__ int    g_csrc[EMAX];
__device__ float  g_invdeg[NMAX];
__device__ double g_colsum[F];
__device__ double g_colsq [F];
__device__ float  g_scale[F];
__device__ float  g_shift[F];

// ---------------- CSR build ----------------
__global__ void zero_deg_kernel(int n) {
    int i = blockIdx.x * blockDim.x + threadIdx.x;
    if (i < n) g_deg[i] = 0;
}

__global__ void hist_kernel(const int* __restrict__ ei, int ne, int n) {
    int e = blockIdx.x * blockDim.x + threadIdx.x;
    if (e < ne) {
        int d = ei[ne + e];
        if ((unsigned)d < (unsigned)n) atomicAdd(&g_deg[d], 1);
    }
}

// single-block exclusive scan over g_deg -> g_off, plus cursor copy & invdeg
__global__ void scan_kernel(int n, int ne) {
    __shared__ int sh[1024];
    __shared__ int carry_s;
    int tid = threadIdx.x;
    if (tid == 0) carry_s = 0;
    __syncthreads();
    for (int base = 0; base < n; base += 1024) {
        int i = base + tid;
        int v = (i < n) ? g_deg[i] : 0;
        sh[tid] = v;
        __syncthreads();
        // inclusive Hillis-Steele
        #pragma unroll
        for (int d = 1; d < 1024; d <<= 1) {
            int t = 0;
            if (tid >= d) t = sh[tid - d];
            __syncthreads();
            sh[tid] += t;
            __syncthreads();
        }
        if (i < n) {
            int excl = sh[tid] - v;
            int off = carry_s + excl;
            g_off[i] = off;
            g_cur[i] = off;
            g_invdeg[i] = 1.0f / fmaxf((float)v, 1.0f);
        }
        __syncthreads();
        if (tid == 0) carry_s += sh[1023];
        __syncthreads();
    }
    if (tid == 0) g_off[n] = ne;
}

__global__ void fill_kernel(const int* __restrict__ ei, int ne, int n) {
    int e = blockIdx.x * blockDim.x + threadIdx.x;
    if (e < ne) {
        int d = ei[ne + e];
        int s = ei[e];
        if ((unsigned)d < (unsigned)n && (unsigned)s < (unsigned)n) {
            int p = atomicAdd(&g_cur[d], 1);
            g_csrc[p] = s;
        }
    }
}

// ---------------- mean aggregation: one warp per node ----------------
__global__ __launch_bounds__(256) void agg_kernel(const float* __restrict__ feat,
                                                  float* __restrict__ outb, int n) {
    int wid  = threadIdx.x >> 5;
    int lane = threadIdx.x & 31;
    int node = blockIdx.x * 8 + wid;
    if (node >= n) return;
    int beg = g_off[node];
    int end = g_off[node + 1];
    float4 acc = make_float4(0.f, 0.f, 0.f, 0.f);
    for (int e = beg; e < end; e++) {
        int s = g_csrc[e];
        float4 v = *(const float4*)(feat + (size_t)s * F + lane * 4);
        acc.x += v.x; acc.y += v.y; acc.z += v.z; acc.w += v.w;
    }
    float inv = g_invdeg[node];
    acc.x *= inv; acc.y *= inv; acc.z *= inv; acc.w *= inv;
    *(float4*)(outb + (size_t)node * F + lane * 4) = acc;
}

// ---------------- SGEMM: C[n,128] = A[n,128] @ W[128,128] + bias ----------------
#define GBM 128
#define GBK 8
__global__ __launch_bounds__(256) void gemm_kernel(const float* __restrict__ A,
                                                   const float* __restrict__ W,
                                                   const float* __restrict__ bias,
                                                   float* __restrict__ C, int n) {
    __shared__ float As[GBK][GBM];
    __shared__ float Bs[GBK][F];
    int block_row = blockIdx.x * GBM;
    int tid = threadIdx.x;
    int tx = tid & 15, ty = tid >> 4;

    float acc[8][8];
    #pragma unroll
    for (int i = 0; i < 8; i++)
        #pragma unroll
        for (int j = 0; j < 8; j++) acc[i][j] = 0.f;

    int a_row = tid >> 1;
    int a_k   = (tid & 1) * 4;
    int b_k   = tid >> 5;
    int b_col = (tid & 31) * 4;

    for (int k0 = 0; k0 < F; k0 += GBK) {
        float4 av = make_float4(0.f, 0.f, 0.f, 0.f);
        int grow = block_row + a_row;
        if (grow < n) av = *(const float4*)(A + (size_t)grow * F + k0 + a_k);
        As[a_k + 0][a_row] = av.x;
        As[a_k + 1][a_row] = av.y;
        As[a_k + 2][a_row] = av.z;
        As[a_k + 3][a_row] = av.w;
        *(float4*)&Bs[b_k][b_col] = *(const float4*)(W + (size_t)(k0 + b_k) * F + b_col);
        __syncthreads();
        #pragma unroll
        for (int kk = 0; kk < GBK; kk++) {
            float ra[8], rb[8];
            #pragma unroll
            for (int i = 0; i < 8; i++) ra[i] = As[kk][ty * 8 + i];
            #pragma unroll
            for (int j = 0; j < 8; j++) rb[j] = Bs[kk][tx * 8 + j];
            #pragma unroll
            for (int i = 0; i < 8; i++)
                #pragma unroll
                for (int j = 0; j < 8; j++) acc[i][j] += ra[i] * rb[j];
        }
        __syncthreads();
    }
    #pragma unroll
    for (int i = 0; i < 8; i++) {
        int grow = block_row + ty * 8 + i;
        if (grow >= n) break;
        #pragma unroll
        for (int j = 0; j < 8; j += 4) {
            int col = tx * 8 + j;
            float4 o;
            o.x = acc[i][j + 0] + bias[col + 0];
            o.y = acc[i][j + 1] + bias[col + 1];
            o.z = acc[i][j + 2] + bias[col + 2];
            o.w = acc[i][j + 3] + bias[col + 3];
            *(float4*)(C + (size_t)grow * F + col) = o;
        }
    }
}

// ---------------- BN ----------------
__global__ void zero_stats_kernel() {
    int i = threadIdx.x;
    if (i < F) { g_colsum[i] = 0.0; g_colsq[i] = 0.0; }
}

__global__ __launch_bounds__(128) void stats_kernel(const float* __restrict__ H, int n) {
    int col = threadIdx.x;
    float s = 0.f, ss = 0.f;
    for (int r = blockIdx.x; r < n; r += gridDim.x) {
        float v = H[(size_t)r * F + col];
        s += v;
        ss += v * v;
    }
    atomicAdd(&g_colsum[col], (double)s);
    atomicAdd(&g_colsq[col], (double)ss);
}

__global__ void finalize_bn_kernel(const float* __restrict__ g,
                                   const float* __restrict__ be, int n) {
    int c = threadIdx.x;
    if (c < F) {
        double mean = g_colsum[c] / (double)n;
        double var  = g_colsq[c] / (double)n - mean * mean;
        float sc = g[c] * rsqrtf((float)var + BN_EPS);
        g_scale[c] = sc;
        g_shift[c] = be[c] - (float)mean * sc;
    }
}

__global__ __launch_bounds__(128) void bnrelu_kernel(const float* __restrict__ in,
                                                     float* __restrict__ outb, int n) {
    int total4 = n * (F / 4);
    int stride = gridDim.x * blockDim.x;
    int idx = blockIdx.x * blockDim.x + threadIdx.x;
    int c4 = (idx & 31) * 4;   // stride is multiple of 32 -> column fixed per thread
    float4 sc = *(const float4*)&g_scale[c4];
    float4 sh = *(const float4*)&g_shift[c4];
    for (; idx < total4; idx += stride) {
        float4 v = ((const float4*)in)[idx];
        float4 o;
        o.x = fmaxf(v.x * sc.x + sh.x, 0.f);
        o.y = fmaxf(v.y * sc.y + sh.y, 0.f);
        o.z = fmaxf(v.z * sc.z + sh.z, 0.f);
        o.w = fmaxf(v.w * sc.w + sh.w, 0.f);
        ((float4*)outb)[idx] = o;
    }
}

// ---------------- classifier + log_softmax: one warp per row ----------------
__global__ __launch_bounds__(256) void classifier_kernel(const float* __restrict__ H,
                                                         const float* __restrict__ Wc,
                                                         const float* __restrict__ bc,
                                                         float* __restrict__ outb, int n) {
    __shared__ float sW[NCLSK * F];   // sW[c*128+f] = Wc[f*40+c]
    for (int idx = threadIdx.x; idx < NCLSK * F; idx += blockDim.x) {
        int c = idx / F, f = idx % F;
        sW[idx] = Wc[f * NCLSK + c];
    }
    __syncthreads();

    int wid = threadIdx.x >> 5;
    int lane = threadIdx.x & 31;
    int nwarps = gridDim.x * (blockDim.x >> 5);
    int gwarp = blockIdx.x * (blockDim.x >> 5) + wid;

    for (int row = gwarp; row < n; row += nwarps) {
        float4 h4 = *(const float4*)(H + (size_t)row * F + lane * 4);
        float l0 = -INFINITY, l1 = -INFINITY;
        #pragma unroll
        for (int c = 0; c < NCLSK; c++) {
            float4 w = *(const float4*)&sW[c * F + lane * 4];
            float p = h4.x * w.x + h4.y * w.y + h4.z * w.z + h4.w * w.w;
            #pragma unroll
            for (int o = 16; o; o >>= 1) p += __shfl_xor_sync(0xffffffffu, p, o);
            p += __ldg(&bc[c]);
            if (c < 32) { if (lane == c) l0 = p; }
            else        { if (lane == c - 32) l1 = p; }
        }
        float m = fmaxf(l0, (lane < 8) ? l1 : -INFINITY);
        #pragma unroll
        for (int o = 16; o; o >>= 1) m = fmaxf(m, __shfl_xor_sync(0xffffffffu, m, o));
        float e = expf(l0 - m) + ((lane < 8) ? expf(l1 - m) : 0.f);
        #pragma unroll
        for (int o = 16; o; o >>= 1) e += __shfl_xor_sync(0xffffffffu, e, o);
        float lse = m + logf(e);
        outb[(size_t)row * NCLSK + lane] = l0 - lse;
        if (lane < 8) outb[(size_t)row * NCLSK + 32 + lane] = l1 - lse;
    }
}

// ---------------- launch ----------------
extern "C" void kernel_launch(void* const* d_in, const int* in_sizes, int n_in,
                              void* d_out, int out_size) {
    const float* x  = (const float*)d_in[0];
    const int*   ei = (const int*)d_in[1];     // int32: JAX x64 disabled
    const float* W0 = (const float*)d_in[2];
    const float* b0 = (const float*)d_in[3];
    const float* g0 = (const float*)d_in[4];
    const float* be0 = (const float*)d_in[5];
    const float* W1 = (const float*)d_in[6];
    const float* b1 = (const float*)d_in[7];
    const float* g1 = (const float*)d_in[8];
    const float* be1 = (const float*)d_in[9];
    const float* Wc = (const float*)d_in[10];
    const float* bc = (const float*)d_in[11];
    float* out = (float*)d_out;

    int n  = in_sizes[0] / F;
    int ne = in_sizes[1] / 2;

    void *p_agg, *p_hlin, *p_h;
    cudaGetSymbolAddress(&p_agg, g_agg);
    cudaGetSymbolAddress(&p_hlin, g_hlin);
    cudaGetSymbolAddress(&p_h, g_h);
    float* aggp  = (float*)p_agg;
    float* hlinp = (float*)p_hlin;
    float* hp    = (float*)p_h;

    // CSR build (shared by both conv layers)
    zero_deg_kernel<<<(n + 255) / 256, 256>>>(n);
    hist_kernel<<<(ne + 255) / 256, 256>>>(ei, ne, n);
    scan_kernel<<<1, 1024>>>(n, ne);
    fill_kernel<<<(ne + 255) / 256, 256>>>(ei, ne, n);

    int agg_blocks  = (n + 7) / 8;
    int gemm_blocks = (n + GBM - 1) / GBM;

    // ---- layer 0 ----
    agg_kernel<<<agg_blocks, 256>>>(x, aggp, n);
    gemm_kernel<<<gemm_blocks, 256>>>(aggp, W0, b0, hlinp, n);
    zero_stats_kernel<<<1, 128>>>();
    stats_kernel<<<512, 128>>>(hlinp, n);
    finalize_bn_kernel<<<1, 128>>>(g0, be0, n);
    bnrelu_kernel<<<2048, 128>>>(hlinp, hp, n);

    // ---- layer 1 ----
    agg_kernel<<<agg_blocks, 256>>>(hp, aggp, n);
    gemm_kernel<<<gemm_blocks, 256>>>(aggp, W1, b1, hlinp, n);
    zero_stats_kernel<<<1, 128>>>();
    stats_kernel<<<512, 128>>>(hlinp, n);
    finalize_bn_kernel<<<1, 128>>>(g1, be1, n);
    bnrelu_kernel<<<2048, 128>>>(hlinp, hp, n);

    // ---- classifier + log_softmax ----
    classifier_kernel<<<1184, 256>>>(hp, Wc, bc, out, n);
}

// round 3
// speedup vs baseline: 1.2162x; 1.2162x over previous
#include <cuda_runtime.h>
#include <math.h>

#define NMAX 50000
#define EMAX 600000
#define F    128
#define NCLSK 40
#define BN_EPS 1e-5f

// ---------------- scratch (device globals; no allocation allowed) ----------------
__device__ float  g_agg [NMAX * F];   // aggregation output / GEMM input
__device__ float  g_hlin[NMAX * F];   // GEMM output (pre-BN)
__device__ int    g_deg [NMAX];
__device__ int    g_off [NMAX];
__device__ int    g_cur [NMAX];
__device__ int    g_csrc[EMAX];
__device__ float  g_invdeg[NMAX];
__device__ float  g_stats[2 * F];     // [0..127]=colsum, [128..255]=colsumsq
__device__ float  g_scale[F];
__device__ float  g_shift[F];
__device__ int    g_counter;

// ---------------- histogram (+ zero stats/counter piggyback) ----------------
__global__ void hist_kernel(const int* __restrict__ ei, int ne, int n) {
    if (blockIdx.x == 0) {
        if (threadIdx.x < 2 * F) g_stats[threadIdx.x] = 0.f;
        if (threadIdx.x == 0) g_counter = 0;
    }
    int e = blockIdx.x * blockDim.x + threadIdx.x;
    if (e < ne) {
        int d = ei[ne + e];
        if ((unsigned)d < (unsigned)n) atomicAdd(&g_deg[d], 1);
    }
}

// ---------------- one-pass block scan with atomic base ----------------
// Block bases come from an atomic counter: not globally ordered, but each
// node's [off, off+deg) segment is disjoint, which is all aggregation needs.
__global__ __launch_bounds__(256) void scan_blocks_kernel(int n) {
    int tid = threadIdx.x;
    int i = blockIdx.x * 256 + tid;
    int v = (i < n) ? g_deg[i] : 0;

    // warp inclusive scan
    int incl = v;
    #pragma unroll
    for (int o = 1; o < 32; o <<= 1) {
        int t = __shfl_up_sync(0xffffffffu, incl, o);
        if ((tid & 31) >= o) incl += t;
    }
    __shared__ int wsum[8];
    if ((tid & 31) == 31) wsum[tid >> 5] = incl;
    __syncthreads();
    if (tid < 8) {
        int w = wsum[tid];
        int s = w;
        #pragma unroll
        for (int o = 1; o < 8; o <<= 1) {
            int t = __shfl_up_sync(0x000000ffu, s, o);
            if (tid >= o) s += t;
        }
        wsum[tid] = s - w;   // exclusive warp offset
    }
    __syncthreads();
    incl += wsum[tid >> 5];

    __shared__ int base_s;
    if (tid == 255) base_s = atomicAdd(&g_counter, incl);
    __syncthreads();

    if (i < n) {
        int off = base_s + incl - v;
        g_off[i] = off;
        g_cur[i] = off;
        g_invdeg[i] = 1.0f / fmaxf((float)v, 1.0f);
    }
}

__global__ void fill_kernel(const int* __restrict__ ei, int ne, int n) {
    int e = blockIdx.x * blockDim.x + threadIdx.x;
    if (e < ne) {
        int d = ei[ne + e];
        int s = ei[e];
        if ((unsigned)d < (unsigned)n && (unsigned)s < (unsigned)n) {
            int p = atomicAdd(&g_cur[d], 1);
            g_csrc[p] = s;
        }
    }
}

// ---------------- mean aggregation: one warp per node (raw features) -------
__global__ __launch_bounds__(256) void agg_kernel(const float* __restrict__ feat,
                                                  float* __restrict__ outb, int n) {
    int wid  = threadIdx.x >> 5;
    int lane = threadIdx.x & 31;
    int node = blockIdx.x * 8 + wid;
    if (node >= n) return;
    int beg = g_off[node];
    int end = beg + g_deg[node];
    float4 acc  = make_float4(0.f, 0.f, 0.f, 0.f);
    float4 acc2 = make_float4(0.f, 0.f, 0.f, 0.f);
    int e = beg;
    for (; e + 1 < end; e += 2) {
        int s0 = g_csrc[e], s1 = g_csrc[e + 1];
        float4 v0 = *(const float4*)(feat + (size_t)s0 * F + lane * 4);
        float4 v1 = *(const float4*)(feat + (size_t)s1 * F + lane * 4);
        acc.x  += v0.x; acc.y  += v0.y; acc.z  += v0.z; acc.w  += v0.w;
        acc2.x += v1.x; acc2.y += v1.y; acc2.z += v1.z; acc2.w += v1.w;
    }
    if (e < end) {
        int s0 = g_csrc[e];
        float4 v0 = *(const float4*)(feat + (size_t)s0 * F + lane * 4);
        acc.x += v0.x; acc.y += v0.y; acc.z += v0.z; acc.w += v0.w;
    }
    float inv = g_invdeg[node];
    acc.x = (acc.x + acc2.x) * inv; acc.y = (acc.y + acc2.y) * inv;
    acc.z = (acc.z + acc2.z) * inv; acc.w = (acc.w + acc2.w) * inv;
    *(float4*)(outb + (size_t)node * F + lane * 4) = acc;
}

// ------- mean aggregation with BN+ReLU applied per-edge (layer 1 input) ----
__global__ __launch_bounds__(256) void agg_bn_kernel(const float* __restrict__ feat,
                                                     float* __restrict__ outb, int n) {
    int wid  = threadIdx.x >> 5;
    int lane = threadIdx.x & 31;
    int node = blockIdx.x * 8 + wid;
    if (node >= n) return;
    float4 sc = *(const float4*)&g_scale[lane * 4];
    float4 sh = *(const float4*)&g_shift[lane * 4];
    int beg = g_off[node];
    int end = beg + g_deg[node];
    float4 acc  = make_float4(0.f, 0.f, 0.f, 0.f);
    float4 acc2 = make_float4(0.f, 0.f, 0.f, 0.f);
    int e = beg;
    for (; e + 1 < end; e += 2) {
        int s0 = g_csrc[e], s1 = g_csrc[e + 1];
        float4 v0 = *(const float4*)(feat + (size_t)s0 * F + lane * 4);
        float4 v1 = *(const float4*)(feat + (size_t)s1 * F + lane * 4);
        acc.x  += fmaxf(v0.x * sc.x + sh.x, 0.f);
        acc.y  += fmaxf(v0.y * sc.y + sh.y, 0.f);
        acc.z  += fmaxf(v0.z * sc.z + sh.z, 0.f);
        acc.w  += fmaxf(v0.w * sc.w + sh.w, 0.f);
        acc2.x += fmaxf(v1.x * sc.x + sh.x, 0.f);
        acc2.y += fmaxf(v1.y * sc.y + sh.y, 0.f);
        acc2.z += fmaxf(v1.z * sc.z + sh.z, 0.f);
        acc2.w += fmaxf(v1.w * sc.w + sh.w, 0.f);
    }
    if (e < end) {
        int s0 = g_csrc[e];
        float4 v0 = *(const float4*)(feat + (size_t)s0 * F + lane * 4);
        acc.x += fmaxf(v0.x * sc.x + sh.x, 0.f);
        acc.y += fmaxf(v0.y * sc.y + sh.y, 0.f);
        acc.z += fmaxf(v0.z * sc.z + sh.z, 0.f);
        acc.w += fmaxf(v0.w * sc.w + sh.w, 0.f);
    }
    float inv = g_invdeg[node];
    acc.x = (acc.x + acc2.x) * inv; acc.y = (acc.y + acc2.y) * inv;
    acc.z = (acc.z + acc2.z) * inv; acc.w = (acc.w + acc2.w) * inv;
    *(float4*)(outb + (size_t)node * F + lane * 4) = acc;
}

// -------- SGEMM (double-buffered) + fused BN-stats epilogue -----------------
#define GBM 128
#define GBK 8
__global__ __launch_bounds__(256) void gemm_stats_kernel(const float* __restrict__ A,
                                                         const float* __restrict__ W,
                                                         const float* __restrict__ bias,
                                                         float* __restrict__ C, int n) {
    __shared__ float As[2][GBK][GBM];
    __shared__ float Bs[2][GBK][F];
    __shared__ float s_sum[F];
    __shared__ float s_sq[F];

    int block_row = blockIdx.x * GBM;
    int tid = threadIdx.x;
    int tx = tid & 15, ty = tid >> 4;

    int a_row = tid >> 1;
    int a_k   = (tid & 1) * 4;
    int b_k   = tid >> 5;
    int b_col = (tid & 31) * 4;

    int grow = block_row + a_row;
    bool arow_ok = grow < n;
    const float* aptr = A + (size_t)grow * F + a_k;

    float acc[8][8];
    #pragma unroll
    for (int i = 0; i < 8; i++)
        #pragma unroll
        for (int j = 0; j < 8; j++) acc[i][j] = 0.f;

    // prologue: load tile 0
    float4 av = arow_ok ? *(const float4*)aptr : make_float4(0.f, 0.f, 0.f, 0.f);
    float4 bv = *(const float4*)(W + (size_t)b_k * F + b_col);
    As[0][a_k + 0][a_row] = av.x;
    As[0][a_k + 1][a_row] = av.y;
    As[0][a_k + 2][a_row] = av.z;
    As[0][a_k + 3][a_row] = av.w;
    *(float4*)&Bs[0][b_k][b_col] = bv;
    __syncthreads();

    int buf = 0;
    #pragma unroll
    for (int k0 = 0; k0 < F; k0 += GBK) {
        float4 nav, nbv;
        bool more = (k0 + GBK) < F;
        if (more) {
            nav = arow_ok ? *(const float4*)(aptr + k0 + GBK)
                          : make_float4(0.f, 0.f, 0.f, 0.f);
            nbv = *(const float4*)(W + (size_t)(k0 + GBK + b_k) * F + b_col);
        }
        #pragma unroll
        for (int kk = 0; kk < GBK; kk++) {
            float4 a0 = *(const float4*)&As[buf][kk][ty * 8];
            float4 a1 = *(const float4*)&As[buf][kk][ty * 8 + 4];
            float4 b0 = *(const float4*)&Bs[buf][kk][tx * 8];
            float4 b1 = *(const float4*)&Bs[buf][kk][tx * 8 + 4];
            float ra[8] = {a0.x, a0.y, a0.z, a0.w, a1.x, a1.y, a1.z, a1.w};
            float rb[8] = {b0.x, b0.y, b0.z, b0.w, b1.x, b1.y, b1.z, b1.w};
            #pragma unroll
            for (int i = 0; i < 8; i++)
                #pragma unroll
                for (int j = 0; j < 8; j++) acc[i][j] += ra[i] * rb[j];
        }
        if (more) {
            int nb = buf ^ 1;
            As[nb][a_k + 0][a_row] = nav.x;
            As[nb][a_k + 1][a_row] = nav.y;
            As[nb][a_k + 2][a_row] = nav.z;
            As[nb][a_k + 3][a_row] = nav.w;
            *(float4*)&Bs[nb][b_k][b_col] = nbv;
        }
        __syncthreads();
        buf ^= 1;
    }

    float bias_r[8];
    #pragma unroll
    for (int j = 0; j < 8; j++) bias_r[j] = __ldg(&bias[tx * 8 + j]);

    // write C
    #pragma unroll
    for (int i = 0; i < 8; i++) {
        int r = block_row + ty * 8 + i;
        if (r < n) {
            #pragma unroll
            for (int j = 0; j < 8; j += 4) {
                float4 o;
                o.x = acc[i][j + 0] + bias_r[j + 0];
                o.y = acc[i][j + 1] + bias_r[j + 1];
                o.z = acc[i][j + 2] + bias_r[j + 2];
                o.w = acc[i][j + 3] + bias_r[j + 3];
                *(float4*)(C + (size_t)r * F + tx * 8 + j) = o;
            }
        }
    }

    // fused BN stats
    if (tid < F) { s_sum[tid] = 0.f; s_sq[tid] = 0.f; }
    __syncthreads();
    #pragma unroll
    for (int j = 0; j < 8; j++) {
        int col = tx * 8 + j;
        float ps = 0.f, pq = 0.f;
        #pragma unroll
        for (int i = 0; i < 8; i++) {
            int r = block_row + ty * 8 + i;
            if (r < n) {
                float v = acc[i][j] + bias_r[j];
                ps += v;
                pq += v * v;
            }
        }
        atomicAdd(&s_sum[col], ps);
        atomicAdd(&s_sq[col], pq);
    }
    __syncthreads();
    if (tid < F) {
        atomicAdd(&g_stats[tid], s_sum[tid]);
        atomicAdd(&g_stats[F + tid], s_sq[tid]);
    }
}

// ---------------- BN finalize (also re-zeros stats for the next layer) -----
__global__ void finalize_bn_kernel(const float* __restrict__ g,
                                   const float* __restrict__ be, int n) {
    int c = threadIdx.x;
    if (c < F) {
        float mean = g_stats[c] / (float)n;
        float var  = g_stats[F + c] / (float)n - mean * mean;
        float sc = g[c] * rsqrtf(var + BN_EPS);
        g_scale[c] = sc;
        g_shift[c] = be[c] - mean * sc;
        g_stats[c] = 0.f;
        g_stats[F + c] = 0.f;
    }
}

// ------- classifier + log_softmax with fused BN+ReLU: one warp per row -----
__global__ __launch_bounds__(256) void classifier_kernel(const float* __restrict__ H,
                                                         const float* __restrict__ Wc,
                                                         const float* __restrict__ bc,
                                                         float* __restrict__ outb, int n) {
    __shared__ float sW[NCLSK * F];   // sW[c*128+f] = Wc[f*40+c]
    for (int idx = threadIdx.x; idx < NCLSK * F; idx += blockDim.x) {
        int c = idx / F, f = idx % F;
        sW[idx] = Wc[f * NCLSK + c];
    }
    __syncthreads();

    int wid = threadIdx.x >> 5;
    int lane = threadIdx.x & 31;
    int nwarps = gridDim.x * (blockDim.x >> 5);
    int gwarp = blockIdx.x * (blockDim.x >> 5) + wid;

    float4 sc = *(const float4*)&g_scale[lane * 4];
    float4 sh = *(const float4*)&g_shift[lane * 4];

    for (int row = gwarp; row < n; row += nwarps) {
        float4 h4 = *(const float4*)(H + (size_t)row * F + lane * 4);
        h4.x = fmaxf(h4.x * sc.x + sh.x, 0.f);
        h4.y = fmaxf(h4.y * sc.y + sh.y, 0.f);
        h4.z = fmaxf(h4.z * sc.z + sh.z, 0.f);
        h4.w = fmaxf(h4.w * sc.w + sh.w, 0.f);
        float l0 = -INFINITY, l1 = -INFINITY;
        #pragma unroll
        for (int c = 0; c < NCLSK; c++) {
            float4 w = *(const float4*)&sW[c * F + lane * 4];
            float p = h4.x * w.x + h4.y * w.y + h4.z * w.z + h4.w * w.w;
            #pragma unroll
            for (int o = 16; o; o >>= 1) p += __shfl_xor_sync(0xffffffffu, p, o);
            p += __ldg(&bc[c]);
            if (c < 32) { if (lane == c) l0 = p; }
            else        { if (lane == c - 32) l1 = p; }
        }
        float m = fmaxf(l0, (lane < 8) ? l1 : -INFINITY);
        #pragma unroll
        for (int o = 16; o; o >>= 1) m = fmaxf(m, __shfl_xor_sync(0xffffffffu, m, o));
        float e = expf(l0 - m) + ((lane < 8) ? expf(l1 - m) : 0.f);
        #pragma unroll
        for (int o = 16; o; o >>= 1) e += __shfl_xor_sync(0xffffffffu, e, o);
        float lse = m + logf(e);
        outb[(size_t)row * NCLSK + lane] = l0 - lse;
        if (lane < 8) outb[(size_t)row * NCLSK + 32 + lane] = l1 - lse;
    }
}

// ---------------- launch ----------------
extern "C" void kernel_launch(void* const* d_in, const int* in_sizes, int n_in,
                              void* d_out, int out_size) {
    const float* x  = (const float*)d_in[0];
    const int*   ei = (const int*)d_in[1];     // int32 (JAX x64 disabled)
    const float* W0 = (const float*)d_in[2];
    const float* b0 = (const float*)d_in[3];
    const float* g0 = (const float*)d_in[4];
    const float* be0 = (const float*)d_in[5];
    const float* W1 = (const float*)d_in[6];
    const float* b1 = (const float*)d_in[7];
    const float* g1 = (const float*)d_in[8];
    const float* be1 = (const float*)d_in[9];
    const float* Wc = (const float*)d_in[10];
    const float* bc = (const float*)d_in[11];
    float* out = (float*)d_out;

    int n  = in_sizes[0] / F;
    int ne = in_sizes[1] / 2;

    void *p_agg, *p_hlin, *p_deg;
    cudaGetSymbolAddress(&p_agg, g_agg);
    cudaGetSymbolAddress(&p_hlin, g_hlin);
    cudaGetSymbolAddress(&p_deg, g_deg);
    float* aggp  = (float*)p_agg;
    float* hlinp = (float*)p_hlin;

    // CSR build (shared by both conv layers)
    cudaMemsetAsync(p_deg, 0, (size_t)n * sizeof(int));
    hist_kernel<<<(ne + 255) / 256, 256>>>(ei, ne, n);
    scan_blocks_kernel<<<(n + 255) / 256, 256>>>(n);
    fill_kernel<<<(ne + 255) / 256, 256>>>(ei, ne, n);

    int agg_blocks  = (n + 7) / 8;
    int gemm_blocks = (n + GBM - 1) / GBM;

    // ---- layer 0 ----
    agg_kernel<<<agg_blocks, 256>>>(x, aggp, n);
    gemm_stats_kernel<<<gemm_blocks, 256>>>(aggp, W0, b0, hlinp, n);
    finalize_bn_kernel<<<1, 128>>>(g0, be0, n);

    // ---- layer 1 (BN+ReLU of layer 0 fused into the gather) ----
    agg_bn_kernel<<<agg_blocks, 256>>>(hlinp, aggp, n);
    gemm_stats_kernel<<<gemm_blocks, 256>>>(aggp, W1, b1, hlinp, n);
    finalize_bn_kernel<<<1, 128>>>(g1, be1, n);

    // ---- classifier + log_softmax (BN+ReLU of layer 1 fused) ----
    classifier_kernel<<<1184, 256>>>(hlinp, Wc, bc, out, n);
}

// round 4
// speedup vs baseline: 1.8822x; 1.5476x over previous
#include <cuda_runtime.h>
#include <math.h>

#define NMAX 50000
#define EMAX 600000
#define F    128
#define NCLSK 40
#define BN_EPS 1e-5f

typedef unsigned long long u64;

// ---------------- packed f32x2 helpers ----------------
__device__ __forceinline__ u64 pack_dup(float a) {
    u64 r;
    asm("mov.b64 %0, {%1, %1};" : "=l"(r) : "f"(a));
    return r;
}
__device__ __forceinline__ void ffma2(u64 &d, u64 a, u64 b) {
    asm("fma.rn.f32x2 %0, %1, %2, %0;" : "+l"(d) : "l"(a), "l"(b));
}
__device__ __forceinline__ float2 unpack2(u64 v) {
    float lo, hi;
    asm("mov.b64 {%0, %1}, %2;" : "=f"(lo), "=f"(hi) : "l"(v));
    return make_float2(lo, hi);
}

// ---------------- scratch (device globals; no allocation allowed) ----------------
__device__ float  g_agg [NMAX * F];   // aggregation output / GEMM input
__device__ float  g_hlin[NMAX * F];   // GEMM output (pre-BN)
__device__ int    g_deg [NMAX];
__device__ int    g_off [NMAX];
__device__ int    g_cur [NMAX];
__device__ int    g_csrc[EMAX];
__device__ float  g_invdeg[NMAX];
__device__ float  g_stats[2 * F];     // [0..127]=colsum, [128..255]=colsumsq
__device__ float  g_scale[F];
__device__ float  g_shift[F];
__device__ int    g_counter;

// ---------------- histogram (+ zero stats/counter piggyback) ----------------
__global__ void hist_kernel(const int* __restrict__ ei, int ne, int n) {
    if (blockIdx.x == 0) {
        if (threadIdx.x < 2 * F) g_stats[threadIdx.x] = 0.f;
        if (threadIdx.x == 0) g_counter = 0;
    }
    int e = blockIdx.x * blockDim.x + threadIdx.x;
    if (e < ne) {
        int d = ei[ne + e];
        if ((unsigned)d < (unsigned)n) atomicAdd(&g_deg[d], 1);
    }
}

// ---------------- one-pass block scan with atomic base ----------------
__global__ __launch_bounds__(256) void scan_blocks_kernel(int n) {
    int tid = threadIdx.x;
    int i = blockIdx.x * 256 + tid;
    int v = (i < n) ? g_deg[i] : 0;

    int incl = v;
    #pragma unroll
    for (int o = 1; o < 32; o <<= 1) {
        int t = __shfl_up_sync(0xffffffffu, incl, o);
        if ((tid & 31) >= o) incl += t;
    }
    __shared__ int wsum[8];
    if ((tid & 31) == 31) wsum[tid >> 5] = incl;
    __syncthreads();
    if (tid < 8) {
        int w = wsum[tid];
        int s = w;
        #pragma unroll
        for (int o = 1; o < 8; o <<= 1) {
            int t = __shfl_up_sync(0x000000ffu, s, o);
            if (tid >= o) s += t;
        }
        wsum[tid] = s - w;
    }
    __syncthreads();
    incl += wsum[tid >> 5];

    __shared__ int base_s;
    if (tid == 255) base_s = atomicAdd(&g_counter, incl);
    __syncthreads();

    if (i < n) {
        int off = base_s + incl - v;
        g_off[i] = off;
        g_cur[i] = off;
        g_invdeg[i] = 1.0f / fmaxf((float)v, 1.0f);
    }
}

__global__ void fill_kernel(const int* __restrict__ ei, int ne, int n) {
    int e = blockIdx.x * blockDim.x + threadIdx.x;
    if (e < ne) {
        int d = ei[ne + e];
        int s = ei[e];
        if ((unsigned)d < (unsigned)n && (unsigned)s < (unsigned)n) {
            int p = atomicAdd(&g_cur[d], 1);
            g_csrc[p] = s;
        }
    }
}

// ---------------- mean aggregation: one warp per node (raw features) -------
__global__ __launch_bounds__(256) void agg_kernel(const float* __restrict__ feat,
                                                  float* __restrict__ outb, int n) {
    int wid  = threadIdx.x >> 5;
    int lane = threadIdx.x & 31;
    int node = blockIdx.x * 8 + wid;
    if (node >= n) return;
    int beg = g_off[node];
    int end = beg + g_deg[node];
    float4 acc  = make_float4(0.f, 0.f, 0.f, 0.f);
    float4 acc2 = make_float4(0.f, 0.f, 0.f, 0.f);
    int e = beg;
    for (; e + 1 < end; e += 2) {
        int s0 = g_csrc[e], s1 = g_csrc[e + 1];
        float4 v0 = *(const float4*)(feat + (size_t)s0 * F + lane * 4);
        float4 v1 = *(const float4*)(feat + (size_t)s1 * F + lane * 4);
        acc.x  += v0.x; acc.y  += v0.y; acc.z  += v0.z; acc.w  += v0.w;
        acc2.x += v1.x; acc2.y += v1.y; acc2.z += v1.z; acc2.w += v1.w;
    }
    if (e < end) {
        int s0 = g_csrc[e];
        float4 v0 = *(const float4*)(feat + (size_t)s0 * F + lane * 4);
        acc.x += v0.x; acc.y += v0.y; acc.z += v0.z; acc.w += v0.w;
    }
    float inv = g_invdeg[node];
    acc.x = (acc.x + acc2.x) * inv; acc.y = (acc.y + acc2.y) * inv;
    acc.z = (acc.z + acc2.z) * inv; acc.w = (acc.w + acc2.w) * inv;
    *(float4*)(outb + (size_t)node * F + lane * 4) = acc;
}

// ------- mean aggregation with BN+ReLU applied per-edge (layer 1 input) ----
__global__ __launch_bounds__(256) void agg_bn_kernel(const float* __restrict__ feat,
                                                     float* __restrict__ outb, int n) {
    int wid  = threadIdx.x >> 5;
    int lane = threadIdx.x & 31;
    int node = blockIdx.x * 8 + wid;
    if (node >= n) return;
    float4 sc = *(const float4*)&g_scale[lane * 4];
    float4 sh = *(const float4*)&g_shift[lane * 4];
    int beg = g_off[node];
    int end = beg + g_deg[node];
    float4 acc  = make_float4(0.f, 0.f, 0.f, 0.f);
    float4 acc2 = make_float4(0.f, 0.f, 0.f, 0.f);
    int e = beg;
    for (; e + 1 < end; e += 2) {
        int s0 = g_csrc[e], s1 = g_csrc[e + 1];
        float4 v0 = *(const float4*)(feat + (size_t)s0 * F + lane * 4);
        float4 v1 = *(const float4*)(feat + (size_t)s1 * F + lane * 4);
        acc.x  += fmaxf(v0.x * sc.x + sh.x, 0.f);
        acc.y  += fmaxf(v0.y * sc.y + sh.y, 0.f);
        acc.z  += fmaxf(v0.z * sc.z + sh.z, 0.f);
        acc.w  += fmaxf(v0.w * sc.w + sh.w, 0.f);
        acc2.x += fmaxf(v1.x * sc.x + sh.x, 0.f);
        acc2.y += fmaxf(v1.y * sc.y + sh.y, 0.f);
        acc2.z += fmaxf(v1.z * sc.z + sh.z, 0.f);
        acc2.w += fmaxf(v1.w * sc.w + sh.w, 0.f);
    }
    if (e < end) {
        int s0 = g_csrc[e];
        float4 v0 = *(const float4*)(feat + (size_t)s0 * F + lane * 4);
        acc.x += fmaxf(v0.x * sc.x + sh.x, 0.f);
        acc.y += fmaxf(v0.y * sc.y + sh.y, 0.f);
        acc.z += fmaxf(v0.z * sc.z + sh.z, 0.f);
        acc.w += fmaxf(v0.w * sc.w + sh.w, 0.f);
    }
    float inv = g_invdeg[node];
    acc.x = (acc.x + acc2.x) * inv; acc.y = (acc.y + acc2.y) * inv;
    acc.z = (acc.z + acc2.z) * inv; acc.w = (acc.w + acc2.w) * inv;
    *(float4*)(outb + (size_t)node * F + lane * 4) = acc;
}

// -------- SGEMM (double-buffered, f32x2 FMA) + fused BN-stats epilogue ------
#define GBM 128
#define GBK 8
__global__ __launch_bounds__(256) void gemm_stats_kernel(const float* __restrict__ A,
                                                         const float* __restrict__ W,
                                                         const float* __restrict__ bias,
                                                         float* __restrict__ C, int n) {
    __shared__ float As[2][GBK][GBM];
    __shared__ float Bs[2][GBK][F];
    __shared__ float s_sum[F];
    __shared__ float s_sq[F];

    int block_row = blockIdx.x * GBM;
    int tid = threadIdx.x;
    int tx = tid & 15, ty = tid >> 4;

    int a_row = tid >> 1;
    int a_k   = (tid & 1) * 4;
    int b_k   = tid >> 5;
    int b_col = (tid & 31) * 4;

    int grow = block_row + a_row;
    bool arow_ok = grow < n;
    const float* aptr = A + (size_t)grow * F + a_k;

    u64 acc2[8][4];
    #pragma unroll
    for (int i = 0; i < 8; i++)
        #pragma unroll
        for (int j = 0; j < 4; j++) acc2[i][j] = 0ULL;

    // prologue: load tile 0
    float4 av = arow_ok ? *(const float4*)aptr : make_float4(0.f, 0.f, 0.f, 0.f);
    float4 bv = *(const float4*)(W + (size_t)b_k * F + b_col);
    As[0][a_k + 0][a_row] = av.x;
    As[0][a_k + 1][a_row] = av.y;
    As[0][a_k + 2][a_row] = av.z;
    As[0][a_k + 3][a_row] = av.w;
    *(float4*)&Bs[0][b_k][b_col] = bv;
    __syncthreads();

    int buf = 0;
    #pragma unroll
    for (int k0 = 0; k0 < F; k0 += GBK) {
        float4 nav, nbv;
        bool more = (k0 + GBK) < F;
        if (more) {
            nav = arow_ok ? *(const float4*)(aptr + k0 + GBK)
                          : make_float4(0.f, 0.f, 0.f, 0.f);
            nbv = *(const float4*)(W + (size_t)(k0 + GBK + b_k) * F + b_col);
        }
        #pragma unroll
        for (int kk = 0; kk < GBK; kk++) {
            float4 a0 = *(const float4*)&As[buf][kk][ty * 8];
            float4 a1 = *(const float4*)&As[buf][kk][ty * 8 + 4];
            ulonglong2 b01 = *(const ulonglong2*)&Bs[buf][kk][tx * 8];
            ulonglong2 b23 = *(const ulonglong2*)&Bs[buf][kk][tx * 8 + 4];
            u64 rb[4] = {b01.x, b01.y, b23.x, b23.y};
            u64 ra[8] = {pack_dup(a0.x), pack_dup(a0.y), pack_dup(a0.z), pack_dup(a0.w),
                         pack_dup(a1.x), pack_dup(a1.y), pack_dup(a1.z), pack_dup(a1.w)};
            #pragma unroll
            for (int i = 0; i < 8; i++)
                #pragma unroll
                for (int j = 0; j < 4; j++) ffma2(acc2[i][j], ra[i], rb[j]);
        }
        if (more) {
            int nb = buf ^ 1;
            As[nb][a_k + 0][a_row] = nav.x;
            As[nb][a_k + 1][a_row] = nav.y;
            As[nb][a_k + 2][a_row] = nav.z;
            As[nb][a_k + 3][a_row] = nav.w;
            *(float4*)&Bs[nb][b_k][b_col] = nbv;
        }
        __syncthreads();
        buf ^= 1;
    }

    float bias_r[8];
    #pragma unroll
    for (int j = 0; j < 8; j++) bias_r[j] = __ldg(&bias[tx * 8 + j]);

    if (tid < F) { s_sum[tid] = 0.f; s_sq[tid] = 0.f; }
    __syncthreads();

    float ps[8], pq[8];
    #pragma unroll
    for (int j = 0; j < 8; j++) { ps[j] = 0.f; pq[j] = 0.f; }

    #pragma unroll
    for (int i = 0; i < 8; i++) {
        int r = block_row + ty * 8 + i;
        if (r < n) {
            float va[8];
            #pragma unroll
            for (int jp = 0; jp < 4; jp++) {
                float2 p = unpack2(acc2[i][jp]);
                va[jp * 2 + 0] = p.x + bias_r[jp * 2 + 0];
                va[jp * 2 + 1] = p.y + bias_r[jp * 2 + 1];
            }
            #pragma unroll
            for (int j = 0; j < 8; j += 4) {
                float4 o = make_float4(va[j], va[j + 1], va[j + 2], va[j + 3]);
                *(float4*)(C + (size_t)r * F + tx * 8 + j) = o;
            }
            #pragma unroll
            for (int j = 0; j < 8; j++) { ps[j] += va[j]; pq[j] += va[j] * va[j]; }
        }
    }
    #pragma unroll
    for (int j = 0; j < 8; j++) {
        atomicAdd(&s_sum[tx * 8 + j], ps[j]);
        atomicAdd(&s_sq[tx * 8 + j], pq[j]);
    }
    __syncthreads();
    if (tid < F) {
        atomicAdd(&g_stats[tid], s_sum[tid]);
        atomicAdd(&g_stats[F + tid], s_sq[tid]);
    }
}

// ---------------- BN finalize (also re-zeros stats for the next layer) -----
__global__ void finalize_bn_kernel(const float* __restrict__ g,
                                   const float* __restrict__ be, int n) {
    int c = threadIdx.x;
    if (c < F) {
        float mean = g_stats[c] / (float)n;
        float var  = g_stats[F + c] / (float)n - mean * mean;
        float sc = g[c] * rsqrtf(var + BN_EPS);
        g_scale[c] = sc;
        g_shift[c] = be[c] - mean * sc;
        g_stats[c] = 0.f;
        g_stats[F + c] = 0.f;
    }
}

// ------- classifier: GEMM tile (128 rows x 40 cls) + fused BN + log_softmax -
__global__ __launch_bounds__(256) void classifier_kernel(const float* __restrict__ H,
                                                         const float* __restrict__ Wc,
                                                         const float* __restrict__ bc,
                                                         float* __restrict__ outb, int n) {
    __shared__ float sbuf[6400];
    float* As   = sbuf;           // [8][128]   = 1024 floats (k-chunk of BN-ReLU'd H)
    float* Ws   = sbuf + 1024;    // [128][40]  = 5120 floats
    float* s_log = sbuf;          // overlay after k-loop: [128][41] = 5248
    float* s_lse = sbuf + 5248;   // [128]

    int tid = threadIdx.x;
    int row0 = blockIdx.x * 128;

    for (int idx = tid; idx < F * NCLSK; idx += 256) Ws[idx] = Wc[idx];

    int tx = tid & 7;     // 8 col-groups x 5 classes
    int ty = tid >> 3;    // 32 row-groups x 4 rows

    float acc[4][5];
    #pragma unroll
    for (int i = 0; i < 4; i++)
        #pragma unroll
        for (int j = 0; j < 5; j++) acc[i][j] = 0.f;

    int lrow = tid >> 1;          // 0..127
    int seg  = (tid & 1) * 4;     // k sub-offset
    int grow = row0 + lrow;
    bool rok = grow < n;
    const float* hp = H + (size_t)grow * F;

    for (int k0 = 0; k0 < F; k0 += 8) {
        float4 v = make_float4(0.f, 0.f, 0.f, 0.f);
        if (rok) v = *(const float4*)(hp + k0 + seg);
        float4 sc = *(const float4*)&g_scale[k0 + seg];
        float4 sh = *(const float4*)&g_shift[k0 + seg];
        v.x = fmaxf(v.x * sc.x + sh.x, 0.f);
        v.y = fmaxf(v.y * sc.y + sh.y, 0.f);
        v.z = fmaxf(v.z * sc.z + sh.z, 0.f);
        v.w = fmaxf(v.w * sc.w + sh.w, 0.f);
        As[(seg + 0) * 128 + lrow] = v.x;
        As[(seg + 1) * 128 + lrow] = v.y;
        As[(seg + 2) * 128 + lrow] = v.z;
        As[(seg + 3) * 128 + lrow] = v.w;
        __syncthreads();
        #pragma unroll
        for (int kk = 0; kk < 8; kk++) {
            float ra[4], rb[5];
            #pragma unroll
            for (int i = 0; i < 4; i++) ra[i] = As[kk * 128 + ty * 4 + i];
            #pragma unroll
            for (int j = 0; j < 5; j++) rb[j] = Ws[(k0 + kk) * NCLSK + tx * 5 + j];
            #pragma unroll
            for (int i = 0; i < 4; i++)
                #pragma unroll
                for (int j = 0; j < 5; j++) acc[i][j] += ra[i] * rb[j];
        }
        __syncthreads();
    }

    float bias_r[5];
    #pragma unroll
    for (int j = 0; j < 5; j++) bias_r[j] = __ldg(&bc[tx * 5 + j]);

    #pragma unroll
    for (int i = 0; i < 4; i++)
        #pragma unroll
        for (int j = 0; j < 5; j++)
            s_log[(ty * 4 + i) * 41 + tx * 5 + j] = acc[i][j] + bias_r[j];
    __syncthreads();

    if (tid < 128) {
        float m = -INFINITY;
        #pragma unroll
        for (int c = 0; c < NCLSK; c++) m = fmaxf(m, s_log[tid * 41 + c]);
        float s = 0.f;
        #pragma unroll
        for (int c = 0; c < NCLSK; c++) s += __expf(s_log[tid * 41 + c] - m);
        s_lse[tid] = m + __logf(s);
    }
    __syncthreads();

    int rows = n - row0;
    if (rows > 128) rows = 128;
    int total = rows * NCLSK;
    for (int idx = tid; idx < total; idx += 256) {
        int r = idx / NCLSK;
        int c = idx - r * NCLSK;
        outb[(size_t)(row0 + r) * NCLSK + c] = s_log[r * 41 + c] - s_lse[r];
    }
}

// ---------------- launch ----------------
extern "C" void kernel_launch(void* const* d_in, const int* in_sizes, int n_in,
                              void* d_out, int out_size) {
    const float* x  = (const float*)d_in[0];
    const int*   ei = (const int*)d_in[1];     // int32 (JAX x64 disabled)
    const float* W0 = (const float*)d_in[2];
    const float* b0 = (const float*)d_in[3];
    const float* g0 = (const float*)d_in[4];
    const float* be0 = (const float*)d_in[5];
    const float* W1 = (const float*)d_in[6];
    const float* b1 = (const float*)d_in[7];
    const float* g1 = (const float*)d_in[8];
    const float* be1 = (const float*)d_in[9];
    const float* Wc = (const float*)d_in[10];
    const float* bc = (const float*)d_in[11];
    float* out = (float*)d_out;

    int n  = in_sizes[0] / F;
    int ne = in_sizes[1] / 2;

    void *p_agg, *p_hlin, *p_deg;
    cudaGetSymbolAddress(&p_agg, g_agg);
    cudaGetSymbolAddress(&p_hlin, g_hlin);
    cudaGetSymbolAddress(&p_deg, g_deg);
    float* aggp  = (float*)p_agg;
    float* hlinp = (float*)p_hlin;

    // CSR build (shared by both conv layers)
    cudaMemsetAsync(p_deg, 0, (size_t)n * sizeof(int));
    hist_kernel<<<(ne + 255) / 256, 256>>>(ei, ne, n);
    scan_blocks_kernel<<<(n + 255) / 256, 256>>>(n);
    fill_kernel<<<(ne + 255) / 256, 256>>>(ei, ne, n);

    int agg_blocks  = (n + 7) / 8;
    int gemm_blocks = (n + GBM - 1) / GBM;

    // ---- layer 0 ----
    agg_kernel<<<agg_blocks, 256>>>(x, aggp, n);
    gemm_stats_kernel<<<gemm_blocks, 256>>>(aggp, W0, b0, hlinp, n);
    finalize_bn_kernel<<<1, 128>>>(g0, be0, n);

    // ---- layer 1 (BN+ReLU of layer 0 fused into the gather) ----
    agg_bn_kernel<<<agg_blocks, 256>>>(hlinp, aggp, n);
    gemm_stats_kernel<<<gemm_blocks, 256>>>(aggp, W1, b1, hlinp, n);
    finalize_bn_kernel<<<1, 128>>>(g1, be1, n);

    // ---- classifier: fused BN+ReLU + GEMM + log_softmax ----
    classifier_kernel<<<gemm_blocks, 256>>>(hlinp, Wc, bc, out, n);
}